// round 1
// baseline (speedup 1.0000x reference)
#include <cuda_runtime.h>
#include <math.h>

// Problem dims (fixed by the dataset)
#define B_DIM 64
#define T_DIM 2048
#define D_DIM 256
#define M_DIM (B_DIM * T_DIM)   // 131072 rows
#define EPS 1e-7f

// GEMM tiling
#define BM 128
#define BN 64
#define BK 32
#define AS_LD 132   // padded leading dim (16B-aligned rows: 132*4 = 528 = 33*16)

// Scratch (no allocations allowed -> device globals)
__device__ float g_scores[M_DIM];
__device__ float g_weights[M_DIM];

// ---------------------------------------------------------------------------
// Kernel 0: zero scores scratch + output (d_out is poisoned by harness)
// ---------------------------------------------------------------------------
__global__ void zero_kernel(float* __restrict__ scores, float* __restrict__ out) {
    int i = blockIdx.x * blockDim.x + threadIdx.x;
    if (i < M_DIM) scores[i] = 0.0f;
    if (i < B_DIM * D_DIM) out[i] = 0.0f;
}

// ---------------------------------------------------------------------------
// Kernel 1: fused GEMM + tanh + uw-dot.
// Computes partial score(m) = sum_{n in [n0,n0+64)} tanh(x[m,:]@W[:,n] + b[n]) * uw[n]
// for a 128-row block, atomically accumulated into g_scores.
// grid = (M/BM, D/BN), block = 256
// ---------------------------------------------------------------------------
__global__ __launch_bounds__(256) void gemm_score_kernel(
    const float* __restrict__ x,     // [M, 256]
    const float* __restrict__ W,     // [256, 256]
    const float* __restrict__ bias,  // [256]
    const float* __restrict__ uw,    // [256]
    float* __restrict__ scores)      // [M]
{
    __shared__ float As[BK][AS_LD];   // x tile, transposed: As[k][m]
    __shared__ float Bs[BK][BN];      // W tile: Bs[k][n]
    __shared__ float red[BM];

    const int m0 = blockIdx.x * BM;
    const int n0 = blockIdx.y * BN;
    const int tid = threadIdx.x;
    const int tm = tid & 15;    // row-group 0..15  (rows tm*8 .. tm*8+7)
    const int tn = tid >> 4;    // col-group 0..15  (cols tn*4 .. tn*4+3)

    float acc[8][4];
#pragma unroll
    for (int i = 0; i < 8; i++)
#pragma unroll
        for (int j = 0; j < 4; j++) acc[i][j] = 0.0f;

    for (int k0 = 0; k0 < D_DIM; k0 += BK) {
        // Load x tile (128 rows x 32 k) as 1024 float4, store transposed
#pragma unroll
        for (int i = 0; i < 4; i++) {
            int f4 = tid + i * 256;
            int r  = f4 >> 3;          // 0..127
            int c4 = f4 & 7;           // 0..7 (float4 within 32 k's)
            float4 v = *(const float4*)&x[(size_t)(m0 + r) * D_DIM + k0 + c4 * 4];
            As[c4 * 4 + 0][r] = v.x;
            As[c4 * 4 + 1][r] = v.y;
            As[c4 * 4 + 2][r] = v.z;
            As[c4 * 4 + 3][r] = v.w;
        }
        // Load W tile (32 k x 64 n) as 512 float4
#pragma unroll
        for (int i = 0; i < 2; i++) {
            int f4 = tid + i * 256;
            int r  = f4 >> 4;          // 0..31
            int c4 = f4 & 15;          // 0..15
            float4 v = *(const float4*)&W[(size_t)(k0 + r) * D_DIM + n0 + c4 * 4];
            *(float4*)&Bs[r][c4 * 4] = v;
        }
        __syncthreads();

#pragma unroll
        for (int kk = 0; kk < BK; kk++) {
            float4 a0 = *(const float4*)&As[kk][tm * 8];
            float4 a1 = *(const float4*)&As[kk][tm * 8 + 4];
            float4 bv = *(const float4*)&Bs[kk][tn * 4];
            float a[8] = {a0.x, a0.y, a0.z, a0.w, a1.x, a1.y, a1.z, a1.w};
            float bb[4] = {bv.x, bv.y, bv.z, bv.w};
#pragma unroll
            for (int i = 0; i < 8; i++)
#pragma unroll
                for (int j = 0; j < 4; j++)
                    acc[i][j] = fmaf(a[i], bb[j], acc[i][j]);
        }
        __syncthreads();
    }

    // Epilogue: tanh(acc + b) * uw, reduce over the 4 local columns
    float p[8];
#pragma unroll
    for (int i = 0; i < 8; i++) {
        float s = 0.0f;
#pragma unroll
        for (int j = 0; j < 4; j++) {
            int n = n0 + tn * 4 + j;
            s += tanhf(acc[i][j] + bias[n]) * uw[n];
        }
        p[i] = s;
    }

    // Reduce across the 16 col-groups (tn) per row via shared atomics
    if (tid < BM) red[tid] = 0.0f;
    __syncthreads();
#pragma unroll
    for (int i = 0; i < 8; i++)
        atomicAdd(&red[tm * 8 + i], p[i]);
    __syncthreads();

    if (tid < BM)
        atomicAdd(&scores[m0 + tid], red[tid]);
}

// ---------------------------------------------------------------------------
// Kernel 2: per-batch softmax over T (matches reference: raw exp, *mask, +EPS)
// grid = B, block = 256
// ---------------------------------------------------------------------------
__global__ __launch_bounds__(256) void softmax_kernel(
    const float* __restrict__ scores,   // [B, T]
    const int* __restrict__ mask,       // [B, T]
    float* __restrict__ weights)        // [B, T]
{
    __shared__ float sm[256];
    const int b = blockIdx.x;
    const int tid = threadIdx.x;
    const size_t base = (size_t)b * T_DIM;

    float e[T_DIM / 256];
    float s = 0.0f;
#pragma unroll
    for (int i = 0; i < T_DIM / 256; i++) {
        int t = i * 256 + tid;
        float v = expf(scores[base + t]) * (float)mask[base + t];
        e[i] = v;
        s += v;
    }
    sm[tid] = s;
    __syncthreads();
    for (int off = 128; off > 0; off >>= 1) {
        if (tid < off) sm[tid] += sm[tid + off];
        __syncthreads();
    }
    float inv = 1.0f / (sm[0] + EPS);
#pragma unroll
    for (int i = 0; i < T_DIM / 256; i++) {
        int t = i * 256 + tid;
        weights[base + t] = e[i] * inv;
    }
}

// ---------------------------------------------------------------------------
// Kernel 3: out[b,d] = sum_t a[b,t] * x[b,t,d]
// grid = (T/256 chunks, B), block = 256 (thread = d)
// ---------------------------------------------------------------------------
__global__ __launch_bounds__(256) void wsum_kernel(
    const float* __restrict__ x,        // [B, T, D]
    const float* __restrict__ weights,  // [B, T]
    float* __restrict__ out)            // [B, D]
{
    const int b = blockIdx.y;
    const int tbase = blockIdx.x * 256;
    const int d = threadIdx.x;

    const float* xb = x + ((size_t)b * T_DIM + tbase) * D_DIM + d;
    const float* wb = weights + (size_t)b * T_DIM + tbase;

    float acc = 0.0f;
#pragma unroll 8
    for (int tt = 0; tt < 256; tt++) {
        acc = fmaf(__ldg(&wb[tt]), xb[(size_t)tt * D_DIM], acc);
    }
    atomicAdd(&out[b * D_DIM + d], acc);
}

// ---------------------------------------------------------------------------
extern "C" void kernel_launch(void* const* d_in, const int* in_sizes, int n_in,
                              void* d_out, int out_size) {
    const float* x    = (const float*)d_in[0];   // [64, 2048, 256]
    const float* W    = (const float*)d_in[1];   // [256, 256]
    const float* bias = (const float*)d_in[2];   // [256]
    const float* uw   = (const float*)d_in[3];   // [256]
    const int*   mask = (const int*)d_in[4];     // [64, 2048]
    float* out = (float*)d_out;                   // [64, 256]

    float* scores;
    float* weights;
    cudaGetSymbolAddress((void**)&scores, g_scores);
    cudaGetSymbolAddress((void**)&weights, g_weights);

    zero_kernel<<<(M_DIM + 255) / 256, 256>>>(scores, out);

    dim3 g1(M_DIM / BM, D_DIM / BN);   // (1024, 4)
    gemm_score_kernel<<<g1, 256>>>(x, W, bias, uw, scores);

    softmax_kernel<<<B_DIM, 256>>>(scores, mask, weights);

    dim3 g3(T_DIM / 256, B_DIM);       // (8, 64)
    wsum_kernel<<<g3, 256>>>(x, weights, out);
}

// round 2
// speedup vs baseline: 2.5082x; 2.5082x over previous
#include <cuda_runtime.h>
#include <cuda_bf16.h>
#include <math.h>

// Problem dims (fixed)
#define B_DIM 64
#define T_DIM 2048
#define D_DIM 256
#define M_DIM (B_DIM * T_DIM)   // 131072
#define EPS 1e-7f

// GEMM tiling: block computes 128(M) x 256(N=full) with K chunks of 16
#define BM 128
#define BK 16
#define SA 24        // smem row stride (bf16 elems): 16 + 8 pad -> conflict-free

// Scratch (device globals; no allocation allowed)
__device__ float g_scores[M_DIM];
__device__ float g_weights[M_DIM];
__device__ __nv_bfloat16 g_Wt_hi[D_DIM * D_DIM];   // W^T split-hi  [n][k]
__device__ __nv_bfloat16 g_Wt_lo[D_DIM * D_DIM];   // W^T split-lo  [n][k]

// ---------------------------------------------------------------------------
// Prep: zero d_out, split-transpose W into bf16 hi/lo [n][k]
// grid 256 x 256 threads = 65536 threads
// ---------------------------------------------------------------------------
__global__ void prep_kernel(const float* __restrict__ W, float* __restrict__ out) {
    int idx = blockIdx.x * blockDim.x + threadIdx.x;   // 0..65535
    if (idx < B_DIM * D_DIM) out[idx] = 0.0f;
    int k = idx >> 8;
    int n = idx & 255;
    float v = W[k * D_DIM + n];
    __nv_bfloat16 hi = __float2bfloat16_rn(v);
    float r = v - __bfloat162float(hi);
    __nv_bfloat16 lo = __float2bfloat16_rn(r);
    g_Wt_hi[n * D_DIM + k] = hi;
    g_Wt_lo[n * D_DIM + k] = lo;
}

// ---------------------------------------------------------------------------
// GEMM + tanh + uw-dot via mma.sync m16n8k16 bf16 with 3-term split.
// grid = M/128 = 1024 blocks, 512 threads (16 warps: 4 m-warps x 4 n-warps)
// Each warp: 32(M) x 64(N) = 2 m-tiles x 8 n-tiles of m16n8k16.
// Block covers all N=256 -> writes scores directly, no atomics.
// ---------------------------------------------------------------------------
__device__ __forceinline__ void mma16816(float* c, const unsigned* a,
                                         unsigned b0, unsigned b1) {
    asm volatile(
        "mma.sync.aligned.m16n8k16.row.col.f32.bf16.bf16.f32 "
        "{%0,%1,%2,%3}, {%4,%5,%6,%7}, {%8,%9}, {%0,%1,%2,%3};\n"
        : "+f"(c[0]), "+f"(c[1]), "+f"(c[2]), "+f"(c[3])
        : "r"(a[0]), "r"(a[1]), "r"(a[2]), "r"(a[3]), "r"(b0), "r"(b1));
}

__global__ __launch_bounds__(512) void gemm_score_kernel(
    const float* __restrict__ x,      // [M, 256]
    const float* __restrict__ bias,   // [256]
    const float* __restrict__ uw,     // [256]
    float* __restrict__ scores)       // [M]
{
    __shared__ __nv_bfloat16 As_hi[BM * SA];
    __shared__ __nv_bfloat16 As_lo[BM * SA];
    __shared__ __nv_bfloat16 Bs_hi[D_DIM * SA];
    __shared__ __nv_bfloat16 Bs_lo[D_DIM * SA];

    const int m0 = blockIdx.x * BM;
    const int tid = threadIdx.x;
    const int wid = tid >> 5;
    const int lane = tid & 31;
    const int wm = wid >> 2;       // 0..3  (m warp)
    const int wn = wid & 3;        // 0..3  (n warp)
    const int gid = lane >> 2;     // 0..7
    const int tg = lane & 3;       // 0..3

    float acc[2][8][4];
#pragma unroll
    for (int mt = 0; mt < 2; mt++)
#pragma unroll
        for (int nt = 0; nt < 8; nt++)
#pragma unroll
            for (int r = 0; r < 4; r++) acc[mt][nt][r] = 0.0f;

    // x-load indexing: one float4 per thread per chunk
    const int xr = tid >> 2;            // 0..127 row
    const int xc4 = tid & 3;            // 0..3 -> k = xc4*4
    // W-load indexing: one float4 (8 bf16) per thread per array per chunk
    const int wn_row = tid >> 1;        // 0..255
    const int wkq = tid & 1;            // 0..1 -> k offset wkq*8

    for (int k0 = 0; k0 < D_DIM; k0 += BK) {
        // ---- stage x tile (fp32 -> split bf16) ----
        float4 v = *(const float4*)&x[(size_t)(m0 + xr) * D_DIM + k0 + xc4 * 4];
        __nv_bfloat162 h01 = __floats2bfloat162_rn(v.x, v.y);
        __nv_bfloat162 h23 = __floats2bfloat162_rn(v.z, v.w);
        __nv_bfloat162 l01 = __floats2bfloat162_rn(v.x - __bfloat162float(h01.x),
                                                   v.y - __bfloat162float(h01.y));
        __nv_bfloat162 l23 = __floats2bfloat162_rn(v.z - __bfloat162float(h23.x),
                                                   v.w - __bfloat162float(h23.y));
        *(__nv_bfloat162*)&As_hi[xr * SA + xc4 * 4]     = h01;
        *(__nv_bfloat162*)&As_hi[xr * SA + xc4 * 4 + 2] = h23;
        *(__nv_bfloat162*)&As_lo[xr * SA + xc4 * 4]     = l01;
        *(__nv_bfloat162*)&As_lo[xr * SA + xc4 * 4 + 2] = l23;
        // ---- stage W tile (already split bf16, [n][k]) ----
        *(float4*)&Bs_hi[wn_row * SA + wkq * 8] =
            *(const float4*)&g_Wt_hi[wn_row * D_DIM + k0 + wkq * 8];
        *(float4*)&Bs_lo[wn_row * SA + wkq * 8] =
            *(const float4*)&g_Wt_lo[wn_row * D_DIM + k0 + wkq * 8];
        __syncthreads();

        // ---- one k16 mma step ----
        unsigned a_hi[2][4], a_lo[2][4];
#pragma unroll
        for (int mt = 0; mt < 2; mt++) {
            int r = wm * 32 + mt * 16 + gid;
            a_hi[mt][0] = *(const unsigned*)&As_hi[r * SA + tg * 2];
            a_hi[mt][1] = *(const unsigned*)&As_hi[(r + 8) * SA + tg * 2];
            a_hi[mt][2] = *(const unsigned*)&As_hi[r * SA + tg * 2 + 8];
            a_hi[mt][3] = *(const unsigned*)&As_hi[(r + 8) * SA + tg * 2 + 8];
            a_lo[mt][0] = *(const unsigned*)&As_lo[r * SA + tg * 2];
            a_lo[mt][1] = *(const unsigned*)&As_lo[(r + 8) * SA + tg * 2];
            a_lo[mt][2] = *(const unsigned*)&As_lo[r * SA + tg * 2 + 8];
            a_lo[mt][3] = *(const unsigned*)&As_lo[(r + 8) * SA + tg * 2 + 8];
        }
#pragma unroll
        for (int nt = 0; nt < 8; nt++) {
            int n = wn * 64 + nt * 8 + gid;
            unsigned bh0 = *(const unsigned*)&Bs_hi[n * SA + tg * 2];
            unsigned bh1 = *(const unsigned*)&Bs_hi[n * SA + tg * 2 + 8];
            unsigned bl0 = *(const unsigned*)&Bs_lo[n * SA + tg * 2];
            unsigned bl1 = *(const unsigned*)&Bs_lo[n * SA + tg * 2 + 8];
#pragma unroll
            for (int mt = 0; mt < 2; mt++) {
                mma16816(acc[mt][nt], a_hi[mt], bh0, bh1);
                mma16816(acc[mt][nt], a_hi[mt], bl0, bl1);
                mma16816(acc[mt][nt], a_lo[mt], bh0, bh1);
            }
        }
        __syncthreads();
    }

    // ---- epilogue: score(m) = sum_n tanh(acc + b[n]) * uw[n] ----
    float* red = (float*)As_hi;   // reuse smem
    if (tid < BM) red[tid] = 0.0f;
    __syncthreads();

    float rowsum[4] = {0.f, 0.f, 0.f, 0.f};   // [mt*2 + (0:row gid, 1:row gid+8)]
#pragma unroll
    for (int nt = 0; nt < 8; nt++) {
        int c0 = wn * 64 + nt * 8 + tg * 2;
        float u0 = __ldg(&uw[c0]), u1 = __ldg(&uw[c0 + 1]);
        float b0 = __ldg(&bias[c0]), b1 = __ldg(&bias[c0 + 1]);
#pragma unroll
        for (int mt = 0; mt < 2; mt++) {
            rowsum[mt * 2 + 0] += tanhf(acc[mt][nt][0] + b0) * u0
                                + tanhf(acc[mt][nt][1] + b1) * u1;
            rowsum[mt * 2 + 1] += tanhf(acc[mt][nt][2] + b0) * u0
                                + tanhf(acc[mt][nt][3] + b1) * u1;
        }
    }
#pragma unroll
    for (int i = 0; i < 4; i++) {
        rowsum[i] += __shfl_xor_sync(0xffffffffu, rowsum[i], 1);
        rowsum[i] += __shfl_xor_sync(0xffffffffu, rowsum[i], 2);
    }
    if (tg == 0) {
        atomicAdd(&red[wm * 32 + gid], rowsum[0]);
        atomicAdd(&red[wm * 32 + gid + 8], rowsum[1]);
        atomicAdd(&red[wm * 32 + 16 + gid], rowsum[2]);
        atomicAdd(&red[wm * 32 + 16 + gid + 8], rowsum[3]);
    }
    __syncthreads();
    if (tid < BM) scores[m0 + tid] = red[tid];
}

// ---------------------------------------------------------------------------
// Softmax over T per batch (reference semantics: raw exp, *mask, +EPS)
// ---------------------------------------------------------------------------
__global__ __launch_bounds__(256) void softmax_kernel(
    const float* __restrict__ scores,
    const int* __restrict__ mask,
    float* __restrict__ weights)
{
    __shared__ float sm[256];
    const int b = blockIdx.x;
    const int tid = threadIdx.x;
    const size_t base = (size_t)b * T_DIM;

    float e[T_DIM / 256];
    float s = 0.0f;
#pragma unroll
    for (int i = 0; i < T_DIM / 256; i++) {
        int t = i * 256 + tid;
        float v = expf(scores[base + t]) * (float)mask[base + t];
        e[i] = v;
        s += v;
    }
    sm[tid] = s;
    __syncthreads();
    for (int off = 128; off > 0; off >>= 1) {
        if (tid < off) sm[tid] += sm[tid + off];
        __syncthreads();
    }
    float inv = 1.0f / (sm[0] + EPS);
#pragma unroll
    for (int i = 0; i < T_DIM / 256; i++) {
        int t = i * 256 + tid;
        weights[base + t] = e[i] * inv;
    }
}

// ---------------------------------------------------------------------------
// out[b,d] = sum_t a[b,t] * x[b,t,d]   (float4 per thread for MLP)
// grid = (T/256, B), block 256: 4 t-groups x 64 d-float4
// ---------------------------------------------------------------------------
__global__ __launch_bounds__(256) void wsum_kernel(
    const float* __restrict__ x,
    const float* __restrict__ weights,
    float* __restrict__ out)
{
    const int b = blockIdx.y;
    const int tbase = blockIdx.x * 256;
    const int d4 = (threadIdx.x & 63);     // float4 index over D
    const int tgrp = threadIdx.x >> 6;     // 0..3

    const float4* xb = (const float4*)(x + ((size_t)b * T_DIM + tbase + tgrp * 64) * D_DIM) + d4;
    const float* wb = weights + (size_t)b * T_DIM + tbase + tgrp * 64;

    float4 acc = make_float4(0.f, 0.f, 0.f, 0.f);
#pragma unroll 8
    for (int i = 0; i < 64; i++) {
        float w = __ldg(&wb[i]);
        float4 v = xb[(size_t)i * (D_DIM / 4)];
        acc.x = fmaf(w, v.x, acc.x);
        acc.y = fmaf(w, v.y, acc.y);
        acc.z = fmaf(w, v.z, acc.z);
        acc.w = fmaf(w, v.w, acc.w);
    }
    float* o = out + b * D_DIM + d4 * 4;
    atomicAdd(o + 0, acc.x);
    atomicAdd(o + 1, acc.y);
    atomicAdd(o + 2, acc.z);
    atomicAdd(o + 3, acc.w);
}

// ---------------------------------------------------------------------------
extern "C" void kernel_launch(void* const* d_in, const int* in_sizes, int n_in,
                              void* d_out, int out_size) {
    const float* x    = (const float*)d_in[0];
    const float* W    = (const float*)d_in[1];
    const float* bias = (const float*)d_in[2];
    const float* uw   = (const float*)d_in[3];
    const int*   mask = (const int*)d_in[4];
    float* out = (float*)d_out;

    float* scores;
    float* weights;
    cudaGetSymbolAddress((void**)&scores, g_scores);
    cudaGetSymbolAddress((void**)&weights, g_weights);

    prep_kernel<<<256, 256>>>(W, out);

    gemm_score_kernel<<<M_DIM / BM, 512>>>(x, bias, uw, scores);

    softmax_kernel<<<B_DIM, 256>>>(scores, mask, weights);

    dim3 g3(T_DIM / 256, B_DIM);
    wsum_kernel<<<g3, 256>>>(x, weights, out);
}

// round 4
// speedup vs baseline: 2.8463x; 1.1348x over previous
#include <cuda_runtime.h>
#include <cuda_bf16.h>
#include <math.h>
#include <stdint.h>

// ---------------- problem dims ----------------
#define B_DIM 64
#define T_DIM 2048
#define D_DIM 256
#define M_DIM (B_DIM * T_DIM)   // 131072
#define EPS 1e-7f

// ---------------- GEMM tiling ----------------
#define BM 128
#define BK 16
#define NIT (D_DIM / BK)        // 16 k-chunks
#define NSTAGE 3
#define SA 24                   // smem row stride in bf16 elems (48B) - conflict-free for ldmatrix
#define SA_B (SA * 2)           // row stride bytes = 48

// per-stage smem (bytes): A_hi 128*48, A_lo 128*48, B_hi 256*48, B_lo 256*48
#define A_HI_OFF(s) ((s) * 36864 + 0)
#define A_LO_OFF(s) ((s) * 36864 + 6144)
#define B_HI_OFF(s) ((s) * 36864 + 12288)
#define B_LO_OFF(s) ((s) * 36864 + 24576)
#define SMEM_TOTAL  (NSTAGE * 36864)     // 110592

// ---------------- scratch globals ----------------
__device__ float g_scores[M_DIM];
__device__ float g_weights[M_DIM];
__device__ __align__(16) __nv_bfloat16 g_Wt_hi[D_DIM * D_DIM];   // [n][k]
__device__ __align__(16) __nv_bfloat16 g_Wt_lo[D_DIM * D_DIM];   // [n][k]

// ---------------- helpers ----------------
__device__ __forceinline__ uint32_t smem_u32(const void* p) {
    uint32_t a;
    asm("{ .reg .u64 t; cvta.to.shared.u64 t, %1; cvt.u32.u64 %0, t; }"
        : "=r"(a) : "l"(p));
    return a;
}

__device__ __forceinline__ void mma16816(float* c, const uint32_t* a,
                                         uint32_t b0, uint32_t b1) {
    asm volatile(
        "mma.sync.aligned.m16n8k16.row.col.f32.bf16.bf16.f32 "
        "{%0,%1,%2,%3}, {%4,%5,%6,%7}, {%8,%9}, {%0,%1,%2,%3};\n"
        : "+f"(c[0]), "+f"(c[1]), "+f"(c[2]), "+f"(c[3])
        : "r"(a[0]), "r"(a[1]), "r"(a[2]), "r"(a[3]), "r"(b0), "r"(b1));
}

__device__ __forceinline__ void ldsm_x4(uint32_t* r, uint32_t addr) {
    asm volatile("ldmatrix.sync.aligned.m8n8.x4.shared.b16 {%0,%1,%2,%3}, [%4];"
        : "=r"(r[0]), "=r"(r[1]), "=r"(r[2]), "=r"(r[3]) : "r"(addr));
}

// ---------------------------------------------------------------------------
// Prep: zero d_out; split-transpose W into bf16 hi/lo [n][k]
// ---------------------------------------------------------------------------
__global__ void prep_kernel(const float* __restrict__ W, float* __restrict__ out) {
    int idx = blockIdx.x * blockDim.x + threadIdx.x;   // 0..65535
    if (idx < B_DIM * D_DIM) out[idx] = 0.0f;
    int k = idx >> 8;
    int n = idx & 255;
    float v = W[k * D_DIM + n];
    __nv_bfloat16 hi = __float2bfloat16_rn(v);
    __nv_bfloat16 lo = __float2bfloat16_rn(v - __bfloat162float(hi));
    g_Wt_hi[n * D_DIM + k] = hi;
    g_Wt_lo[n * D_DIM + k] = lo;
}

// ---------------------------------------------------------------------------
// GEMM + tanh + uw-dot via mma.sync, ldmatrix, 3-stage pipeline.
// grid = M/128 = 1024, block = 512 (16 warps: 4 m x 4 n), warp tile 32x64.
// ---------------------------------------------------------------------------
__global__ __launch_bounds__(512) void gemm_score_kernel(
    const float* __restrict__ x,      // [M, 256]
    const float* __restrict__ bias,   // [256]
    const float* __restrict__ uw,     // [256]
    float* __restrict__ scores)       // [M]
{
    extern __shared__ char smem[];
    __shared__ float red[BM];
    const uint32_t sb = smem_u32(smem);
    const int tid = threadIdx.x;
    const int wid = tid >> 5;
    const int lane = tid & 31;
    const int wm = wid >> 2;       // 0..3
    const int wn = wid & 3;        // 0..3
    const int gid = lane >> 2;     // 0..7
    const int tg = lane & 3;       // 0..3
    const int m0 = blockIdx.x * BM;

    float acc[2][8][4];
#pragma unroll
    for (int mt = 0; mt < 2; mt++)
#pragma unroll
        for (int nt = 0; nt < 8; nt++)
#pragma unroll
            for (int r = 0; r < 4; r++) acc[mt][nt][r] = 0.0f;

    // ---- global-load / smem-store index setup ----
    const int ar = tid >> 2;                 // A row 0..127
    const int akq = tid & 3;                 // A k-quad -> k = akq*4
    const int br = tid >> 1;                 // B row 0..255
    const int bkh = (tid & 1) * 8;           // B k-half 0 or 8
    const uint32_t a_sts = sb + ar * SA_B + akq * 8;      // + A_??_OFF(s)
    const uint32_t b_sts = sb + br * SA_B + bkh * 2;      // + B_??_OFF(s)

    // ---- ldmatrix addresses (within stage; add A/B offset + sb) ----
    // A: rows wm*32 + mt*16 + (lane&15), k-half = lane>>4
    const uint32_t a_lds0 = sb + (wm * 32 + (lane & 15)) * SA_B + (lane >> 4) * 16;
    // B: rows wn*64 + p*16 + (lane&7) + (lane>=16 ? 8 : 0), k-half = (lane>>3)&1
    const uint32_t b_lds0 = sb + (wn * 64 + (lane & 7) + ((lane >> 4) << 3)) * SA_B
                               + ((lane >> 3) & 1) * 16;

    // ---- prefetch registers ----
    float4 pa;           // x chunk
    uint4 pbh, pbl;      // W chunk hi/lo

#define LDG_CHUNK(c)                                                         \
    do {                                                                     \
        int k0 = (c) * BK;                                                   \
        pa  = *(const float4*)&x[(size_t)(m0 + ar) * D_DIM + k0 + akq * 4];  \
        pbh = *(const uint4*)&g_Wt_hi[br * D_DIM + k0 + bkh];                \
        pbl = *(const uint4*)&g_Wt_lo[br * D_DIM + k0 + bkh];                \
    } while (0)

#define STS_CHUNK(s)                                                         \
    do {                                                                     \
        __nv_bfloat162 h01 = __floats2bfloat162_rn(pa.x, pa.y);              \
        __nv_bfloat162 h23 = __floats2bfloat162_rn(pa.z, pa.w);              \
        __nv_bfloat162 l01 = __floats2bfloat162_rn(pa.x - __bfloat162float(h01.x), \
                                                   pa.y - __bfloat162float(h01.y)); \
        __nv_bfloat162 l23 = __floats2bfloat162_rn(pa.z - __bfloat162float(h23.x), \
                                                   pa.w - __bfloat162float(h23.y)); \
        union { __nv_bfloat162 b[2]; uint2 u; } hh, ll;                      \
        hh.b[0] = h01; hh.b[1] = h23;                                        \
        ll.b[0] = l01; ll.b[1] = l23;                                        \
        *(uint2*)(smem + A_HI_OFF(s) + (a_sts - sb)) = hh.u;                 \
        *(uint2*)(smem + A_LO_OFF(s) + (a_sts - sb)) = ll.u;                 \
        *(uint4*)(smem + B_HI_OFF(s) + (b_sts - sb)) = pbh;                  \
        *(uint4*)(smem + B_LO_OFF(s) + (b_sts - sb)) = pbl;                  \
    } while (0)

    // prologue: chunk0 -> stage0, prefetch chunk1
    LDG_CHUNK(0);
    STS_CHUNK(0);
    LDG_CHUNK(1);

    for (int c = 0; c < NIT; c++) {
        const int cur = c % NSTAGE;
        __syncthreads();                       // stage `cur` stores now visible
        if (c + 1 < NIT) {
            STS_CHUNK((c + 1) % NSTAGE);       // stash prefetched chunk
        }
        if (c + 2 < NIT) {
            LDG_CHUNK(c + 2);                  // issue next global loads
        }

        // fragments
        uint32_t a_hi[2][4], a_lo[2][4];
#pragma unroll
        for (int mt = 0; mt < 2; mt++) {
            ldsm_x4(a_hi[mt], a_lds0 + A_HI_OFF(cur) + mt * 16 * SA_B);
            ldsm_x4(a_lo[mt], a_lds0 + A_LO_OFF(cur) + mt * 16 * SA_B);
        }
#pragma unroll
        for (int p = 0; p < 4; p++) {
            uint32_t bh[4], bl[4];
            ldsm_x4(bh, b_lds0 + B_HI_OFF(cur) + p * 16 * SA_B);
            ldsm_x4(bl, b_lds0 + B_LO_OFF(cur) + p * 16 * SA_B);
#pragma unroll
            for (int mt = 0; mt < 2; mt++) {
                mma16816(acc[mt][2 * p],     a_hi[mt], bh[0], bh[1]);
                mma16816(acc[mt][2 * p + 1], a_hi[mt], bh[2], bh[3]);
                mma16816(acc[mt][2 * p],     a_hi[mt], bl[0], bl[1]);
                mma16816(acc[mt][2 * p + 1], a_hi[mt], bl[2], bl[3]);
                mma16816(acc[mt][2 * p],     a_lo[mt], bh[0], bh[1]);
                mma16816(acc[mt][2 * p + 1], a_lo[mt], bh[2], bh[3]);
            }
        }
    }

    // ---- epilogue: score(m) = sum_n tanh(acc + b[n]) * uw[n] ----
    if (tid < BM) red[tid] = 0.0f;
    __syncthreads();

    float rowsum[4] = {0.f, 0.f, 0.f, 0.f};
#pragma unroll
    for (int nt = 0; nt < 8; nt++) {
        int c0 = wn * 64 + nt * 8 + tg * 2;
        float u0 = __ldg(&uw[c0]), u1 = __ldg(&uw[c0 + 1]);
        float b0 = __ldg(&bias[c0]), b1 = __ldg(&bias[c0 + 1]);
#pragma unroll
        for (int mt = 0; mt < 2; mt++) {
            rowsum[mt * 2 + 0] += tanhf(acc[mt][nt][0] + b0) * u0
                                + tanhf(acc[mt][nt][1] + b1) * u1;
            rowsum[mt * 2 + 1] += tanhf(acc[mt][nt][2] + b0) * u0
                                + tanhf(acc[mt][nt][3] + b1) * u1;
        }
    }
#pragma unroll
    for (int i = 0; i < 4; i++) {
        rowsum[i] += __shfl_xor_sync(0xffffffffu, rowsum[i], 1);
        rowsum[i] += __shfl_xor_sync(0xffffffffu, rowsum[i], 2);
    }
    if (tg == 0) {
        atomicAdd(&red[wm * 32 + gid], rowsum[0]);
        atomicAdd(&red[wm * 32 + gid + 8], rowsum[1]);
        atomicAdd(&red[wm * 32 + 16 + gid], rowsum[2]);
        atomicAdd(&red[wm * 32 + 16 + gid + 8], rowsum[3]);
    }
    __syncthreads();
    if (tid < BM) scores[m0 + tid] = red[tid];
}

// ---------------------------------------------------------------------------
// Softmax over T per batch (reference semantics: raw exp, *mask, +EPS)
// ---------------------------------------------------------------------------
__global__ __launch_bounds__(256) void softmax_kernel(
    const float* __restrict__ scores,
    const int* __restrict__ mask,
    float* __restrict__ weights)
{
    __shared__ float sm[256];
    const int b = blockIdx.x;
    const int tid = threadIdx.x;
    const size_t base = (size_t)b * T_DIM;

    float e[T_DIM / 256];
    float s = 0.0f;
#pragma unroll
    for (int i = 0; i < T_DIM / 256; i++) {
        int t = i * 256 + tid;
        float v = expf(scores[base + t]) * (float)mask[base + t];
        e[i] = v;
        s += v;
    }
    sm[tid] = s;
    __syncthreads();
    for (int off = 128; off > 0; off >>= 1) {
        if (tid < off) sm[tid] += sm[tid + off];
        __syncthreads();
    }
    float inv = 1.0f / (sm[0] + EPS);
#pragma unroll
    for (int i = 0; i < T_DIM / 256; i++) {
        int t = i * 256 + tid;
        weights[base + t] = e[i] * inv;
    }
}

// ---------------------------------------------------------------------------
// out[b,d] = sum_t a[b,t] * x[b,t,d]
// grid = (T/128, B), block 256: 2 t-groups x 64 d-float4, 64 t per group
// ---------------------------------------------------------------------------
__global__ __launch_bounds__(256) void wsum_kernel(
    const float* __restrict__ x,
    const float* __restrict__ weights,
    float* __restrict__ out)
{
    const int b = blockIdx.y;
    const int tbase = blockIdx.x * 128;
    const int d4 = (threadIdx.x & 63);
    const int tgrp = threadIdx.x >> 6;     // 0..3 -> 32 t each

    const float4* xb = (const float4*)(x + ((size_t)b * T_DIM + tbase + tgrp * 32) * D_DIM) + d4;
    const float* wb = weights + (size_t)b * T_DIM + tbase + tgrp * 32;

    float4 acc = make_float4(0.f, 0.f, 0.f, 0.f);
#pragma unroll 8
    for (int i = 0; i < 32; i++) {
        float w = __ldg(&wb[i]);
        float4 v = xb[(size_t)i * (D_DIM / 4)];
        acc.x = fmaf(w, v.x, acc.x);
        acc.y = fmaf(w, v.y, acc.y);
        acc.z = fmaf(w, v.z, acc.z);
        acc.w = fmaf(w, v.w, acc.w);
    }
    float* o = out + b * D_DIM + d4 * 4;
    atomicAdd(o + 0, acc.x);
    atomicAdd(o + 1, acc.y);
    atomicAdd(o + 2, acc.z);
    atomicAdd(o + 3, acc.w);
}

// ---------------------------------------------------------------------------
extern "C" void kernel_launch(void* const* d_in, const int* in_sizes, int n_in,
                              void* d_out, int out_size) {
    const float* x    = (const float*)d_in[0];
    const float* W    = (const float*)d_in[1];
    const float* bias = (const float*)d_in[2];
    const float* uw   = (const float*)d_in[3];
    const int*   mask = (const int*)d_in[4];
    float* out = (float*)d_out;

    float* scores;
    float* weights;
    cudaGetSymbolAddress((void**)&scores, g_scores);
    cudaGetSymbolAddress((void**)&weights, g_weights);

    cudaFuncSetAttribute(gemm_score_kernel,
                         cudaFuncAttributeMaxDynamicSharedMemorySize, SMEM_TOTAL);

    prep_kernel<<<256, 256>>>(W, out);

    gemm_score_kernel<<<M_DIM / BM, 512, SMEM_TOTAL>>>(x, bias, uw, scores);

    softmax_kernel<<<B_DIM, 256>>>(scores, mask, weights);

    dim3 g3(T_DIM / 128, B_DIM);
    wsum_kernel<<<g3, 256>>>(x, weights, out);
}

// round 5
// speedup vs baseline: 3.6371x; 1.2779x over previous
#include <cuda_runtime.h>
#include <cuda_fp16.h>
#include <math.h>
#include <stdint.h>

// ---------------- problem dims ----------------
#define B_DIM 64
#define T_DIM 2048
#define D_DIM 256
#define M_DIM (B_DIM * T_DIM)   // 131072
#define EPS 1e-7f
#define WSCALE 16.0f
#define WSCALE_INV 0.0625f

// ---------------- GEMM tiling ----------------
#define BM 128
#define BK 16
#define NIT (D_DIM / BK)        // 16 k-chunks
#define NSTAGE 3
#define SA 24                   // smem row stride in fp16 elems (48B)
#define SA_B (SA * 2)           // 48 bytes

// per-stage smem: A 128*48 = 6144, B_hi 256*48 = 12288, B_lo 12288
#define STAGE_BYTES 30720
#define A_OFF(s)    ((s) * STAGE_BYTES + 0)
#define B_HI_OFF(s) ((s) * STAGE_BYTES + 6144)
#define B_LO_OFF(s) ((s) * STAGE_BYTES + 18432)
#define SMEM_TOTAL  (NSTAGE * STAGE_BYTES)     // 92160

// ---------------- scratch globals ----------------
__device__ float g_scores[M_DIM];
__device__ float g_weights[M_DIM];
__device__ __align__(16) __half g_Wt_hi[D_DIM * D_DIM];   // [n][k], W*16 hi
__device__ __align__(16) __half g_Wt_lo[D_DIM * D_DIM];   // [n][k], W*16 residual

// ---------------- helpers ----------------
__device__ __forceinline__ uint32_t smem_u32(const void* p) {
    uint32_t a;
    asm("{ .reg .u64 t; cvta.to.shared.u64 t, %1; cvt.u32.u64 %0, t; }"
        : "=r"(a) : "l"(p));
    return a;
}

__device__ __forceinline__ void mma16816(float* c, const uint32_t* a,
                                         uint32_t b0, uint32_t b1) {
    asm volatile(
        "mma.sync.aligned.m16n8k16.row.col.f32.f16.f16.f32 "
        "{%0,%1,%2,%3}, {%4,%5,%6,%7}, {%8,%9}, {%0,%1,%2,%3};\n"
        : "+f"(c[0]), "+f"(c[1]), "+f"(c[2]), "+f"(c[3])
        : "r"(a[0]), "r"(a[1]), "r"(a[2]), "r"(a[3]), "r"(b0), "r"(b1));
}

__device__ __forceinline__ void ldsm_x4(uint32_t* r, uint32_t addr) {
    asm volatile("ldmatrix.sync.aligned.m8n8.x4.shared.b16 {%0,%1,%2,%3}, [%4];"
        : "=r"(r[0]), "=r"(r[1]), "=r"(r[2]), "=r"(r[3]) : "r"(addr));
}

// ---------------------------------------------------------------------------
// Prep: zero d_out; split-transpose W*16 into fp16 hi/lo [n][k]
// ---------------------------------------------------------------------------
__global__ void prep_kernel(const float* __restrict__ W, float* __restrict__ out) {
    int idx = blockIdx.x * blockDim.x + threadIdx.x;   // 0..65535
    if (idx < B_DIM * D_DIM) out[idx] = 0.0f;
    int k = idx >> 8;
    int n = idx & 255;
    float v = W[k * D_DIM + n] * WSCALE;
    __half hi = __float2half_rn(v);
    __half lo = __float2half_rn(v - __half2float(hi));
    g_Wt_hi[n * D_DIM + k] = hi;
    g_Wt_lo[n * D_DIM + k] = lo;
}

// ---------------------------------------------------------------------------
// GEMM + tanh + uw-dot: mma.sync f16, 2-term (xh*Wh + xh*Wl), 3-stage pipe.
// grid = M/128 = 1024, block = 512 (16 warps: 4 m x 4 n), warp tile 32x64.
// ---------------------------------------------------------------------------
__global__ __launch_bounds__(512) void gemm_score_kernel(
    const float* __restrict__ x,      // [M, 256]
    const float* __restrict__ bias,   // [256]
    const float* __restrict__ uw,     // [256]
    float* __restrict__ scores)       // [M]
{
    extern __shared__ char smem[];
    __shared__ float red[BM];
    const uint32_t sb = smem_u32(smem);
    const int tid = threadIdx.x;
    const int wid = tid >> 5;
    const int lane = tid & 31;
    const int wm = wid >> 2;       // 0..3
    const int wn = wid & 3;        // 0..3
    const int gid = lane >> 2;     // 0..7
    const int tg = lane & 3;       // 0..3
    const int m0 = blockIdx.x * BM;

    float acc[2][8][4];
#pragma unroll
    for (int mt = 0; mt < 2; mt++)
#pragma unroll
        for (int nt = 0; nt < 8; nt++)
#pragma unroll
            for (int r = 0; r < 4; r++) acc[mt][nt][r] = 0.0f;

    // ---- global-load / smem-store index setup ----
    const int ar = tid >> 2;                 // A row 0..127
    const int akq = tid & 3;                 // A k-quad -> k = akq*4
    const int br = tid >> 1;                 // B row 0..255
    const int bkh = (tid & 1) * 8;           // B k-half 0 or 8
    const uint32_t a_sts_off = ar * SA_B + akq * 8;
    const uint32_t b_sts_off = br * SA_B + bkh * 2;

    // ---- ldmatrix addresses ----
    const uint32_t a_lds0 = sb + (wm * 32 + (lane & 15)) * SA_B + (lane >> 4) * 16;
    const uint32_t b_lds0 = sb + (wn * 64 + (lane & 7) + ((lane >> 4) << 3)) * SA_B
                               + ((lane >> 3) & 1) * 16;

    float4 pa;
    uint4 pbh, pbl;

#define LDG_CHUNK(c)                                                         \
    do {                                                                     \
        int k0 = (c) * BK;                                                   \
        pa  = *(const float4*)&x[(size_t)(m0 + ar) * D_DIM + k0 + akq * 4];  \
        pbh = *(const uint4*)&g_Wt_hi[br * D_DIM + k0 + bkh];                \
        pbl = *(const uint4*)&g_Wt_lo[br * D_DIM + k0 + bkh];                \
    } while (0)

#define STS_CHUNK(s)                                                         \
    do {                                                                     \
        __half2 h01 = __floats2half2_rn(pa.x, pa.y);                         \
        __half2 h23 = __floats2half2_rn(pa.z, pa.w);                         \
        union { __half2 h[2]; uint2 u; } hh;                                 \
        hh.h[0] = h01; hh.h[1] = h23;                                        \
        *(uint2*)(smem + A_OFF(s) + a_sts_off) = hh.u;                       \
        *(uint4*)(smem + B_HI_OFF(s) + b_sts_off) = pbh;                     \
        *(uint4*)(smem + B_LO_OFF(s) + b_sts_off) = pbl;                     \
    } while (0)

    LDG_CHUNK(0);
    STS_CHUNK(0);
    LDG_CHUNK(1);

    for (int c = 0; c < NIT; c++) {
        const int cur = c % NSTAGE;
        __syncthreads();
        if (c + 1 < NIT) STS_CHUNK((c + 1) % NSTAGE);
        if (c + 2 < NIT) LDG_CHUNK(c + 2);

        uint32_t a[2][4];
#pragma unroll
        for (int mt = 0; mt < 2; mt++)
            ldsm_x4(a[mt], a_lds0 + A_OFF(cur) + mt * 16 * SA_B);
#pragma unroll
        for (int p = 0; p < 4; p++) {
            uint32_t bh[4], bl[4];
            ldsm_x4(bh, b_lds0 + B_HI_OFF(cur) + p * 16 * SA_B);
            ldsm_x4(bl, b_lds0 + B_LO_OFF(cur) + p * 16 * SA_B);
#pragma unroll
            for (int mt = 0; mt < 2; mt++) {
                mma16816(acc[mt][2 * p],     a[mt], bh[0], bh[1]);
                mma16816(acc[mt][2 * p + 1], a[mt], bh[2], bh[3]);
                mma16816(acc[mt][2 * p],     a[mt], bl[0], bl[1]);
                mma16816(acc[mt][2 * p + 1], a[mt], bl[2], bl[3]);
            }
        }
    }

    // ---- epilogue: score(m) = sum_n tanh(acc/16 + b[n]) * uw[n] ----
    if (tid < BM) red[tid] = 0.0f;
    __syncthreads();

    float rowsum[4] = {0.f, 0.f, 0.f, 0.f};
#pragma unroll
    for (int nt = 0; nt < 8; nt++) {
        int c0 = wn * 64 + nt * 8 + tg * 2;
        float u0 = __ldg(&uw[c0]), u1 = __ldg(&uw[c0 + 1]);
        float b0 = __ldg(&bias[c0]), b1 = __ldg(&bias[c0 + 1]);
#pragma unroll
        for (int mt = 0; mt < 2; mt++) {
            rowsum[mt * 2 + 0] += tanhf(fmaf(acc[mt][nt][0], WSCALE_INV, b0)) * u0
                                + tanhf(fmaf(acc[mt][nt][1], WSCALE_INV, b1)) * u1;
            rowsum[mt * 2 + 1] += tanhf(fmaf(acc[mt][nt][2], WSCALE_INV, b0)) * u0
                                + tanhf(fmaf(acc[mt][nt][3], WSCALE_INV, b1)) * u1;
        }
    }
#pragma unroll
    for (int i = 0; i < 4; i++) {
        rowsum[i] += __shfl_xor_sync(0xffffffffu, rowsum[i], 1);
        rowsum[i] += __shfl_xor_sync(0xffffffffu, rowsum[i], 2);
    }
    if (tg == 0) {
        atomicAdd(&red[wm * 32 + gid], rowsum[0]);
        atomicAdd(&red[wm * 32 + gid + 8], rowsum[1]);
        atomicAdd(&red[wm * 32 + 16 + gid], rowsum[2]);
        atomicAdd(&red[wm * 32 + 16 + gid + 8], rowsum[3]);
    }
    __syncthreads();
    if (tid < BM) scores[m0 + tid] = red[tid];
}

// ---------------------------------------------------------------------------
// Softmax over T per batch (reference semantics: raw exp, *mask, +EPS)
// ---------------------------------------------------------------------------
__global__ __launch_bounds__(256) void softmax_kernel(
    const float* __restrict__ scores,
    const int* __restrict__ mask,
    float* __restrict__ weights)
{
    __shared__ float sm[256];
    const int b = blockIdx.x;
    const int tid = threadIdx.x;
    const size_t base = (size_t)b * T_DIM;

    float e[T_DIM / 256];
    float s = 0.0f;
#pragma unroll
    for (int i = 0; i < T_DIM / 256; i++) {
        int t = i * 256 + tid;
        float v = expf(scores[base + t]) * (float)mask[base + t];
        e[i] = v;
        s += v;
    }
    sm[tid] = s;
    __syncthreads();
    for (int off = 128; off > 0; off >>= 1) {
        if (tid < off) sm[tid] += sm[tid + off];
        __syncthreads();
    }
    float inv = 1.0f / (sm[0] + EPS);
#pragma unroll
    for (int i = 0; i < T_DIM / 256; i++) {
        int t = i * 256 + tid;
        weights[base + t] = e[i] * inv;
    }
}

// ---------------------------------------------------------------------------
// out[b,d] = sum_t a[b,t] * x[b,t,d]  — 4-deep load batching for MLP
// grid = (T/128, B), block 256: 4 t-groups x 64 d-float4, 32 t each
// ---------------------------------------------------------------------------
__global__ __launch_bounds__(256, 2) void wsum_kernel(
    const float* __restrict__ x,
    const float* __restrict__ weights,
    float* __restrict__ out)
{
    const int b = blockIdx.y;
    const int tbase = blockIdx.x * 128;
    const int d4 = (threadIdx.x & 63);
    const int tgrp = threadIdx.x >> 6;

    const float4* xb = (const float4*)(x + ((size_t)b * T_DIM + tbase + tgrp * 32) * D_DIM) + d4;
    const float* wb = weights + (size_t)b * T_DIM + tbase + tgrp * 32;

    float4 acc = make_float4(0.f, 0.f, 0.f, 0.f);
#pragma unroll
    for (int i = 0; i < 32; i += 4) {
        float w0 = __ldg(&wb[i + 0]);
        float w1 = __ldg(&wb[i + 1]);
        float w2 = __ldg(&wb[i + 2]);
        float w3 = __ldg(&wb[i + 3]);
        float4 v0 = xb[(size_t)(i + 0) * (D_DIM / 4)];
        float4 v1 = xb[(size_t)(i + 1) * (D_DIM / 4)];
        float4 v2 = xb[(size_t)(i + 2) * (D_DIM / 4)];
        float4 v3 = xb[(size_t)(i + 3) * (D_DIM / 4)];
        acc.x = fmaf(w0, v0.x, acc.x); acc.y = fmaf(w0, v0.y, acc.y);
        acc.z = fmaf(w0, v0.z, acc.z); acc.w = fmaf(w0, v0.w, acc.w);
        acc.x = fmaf(w1, v1.x, acc.x); acc.y = fmaf(w1, v1.y, acc.y);
        acc.z = fmaf(w1, v1.z, acc.z); acc.w = fmaf(w1, v1.w, acc.w);
        acc.x = fmaf(w2, v2.x, acc.x); acc.y = fmaf(w2, v2.y, acc.y);
        acc.z = fmaf(w2, v2.z, acc.z); acc.w = fmaf(w2, v2.w, acc.w);
        acc.x = fmaf(w3, v3.x, acc.x); acc.y = fmaf(w3, v3.y, acc.y);
        acc.z = fmaf(w3, v3.z, acc.z); acc.w = fmaf(w3, v3.w, acc.w);
    }
    float* o = out + b * D_DIM + d4 * 4;
    atomicAdd(o + 0, acc.x);
    atomicAdd(o + 1, acc.y);
    atomicAdd(o + 2, acc.z);
    atomicAdd(o + 3, acc.w);
}

// ---------------------------------------------------------------------------
extern "C" void kernel_launch(void* const* d_in, const int* in_sizes, int n_in,
                              void* d_out, int out_size) {
    const float* x    = (const float*)d_in[0];
    const float* W    = (const float*)d_in[1];
    const float* bias = (const float*)d_in[2];
    const float* uw   = (const float*)d_in[3];
    const int*   mask = (const int*)d_in[4];
    float* out = (float*)d_out;

    float* scores;
    float* weights;
    cudaGetSymbolAddress((void**)&scores, g_scores);
    cudaGetSymbolAddress((void**)&weights, g_weights);

    cudaFuncSetAttribute(gemm_score_kernel,
                         cudaFuncAttributeMaxDynamicSharedMemorySize, SMEM_TOTAL);

    prep_kernel<<<256, 256>>>(W, out);

    gemm_score_kernel<<<M_DIM / BM, 512, SMEM_TOTAL>>>(x, bias, uw, scores);

    softmax_kernel<<<B_DIM, 256>>>(scores, mask, weights);

    dim3 g3(T_DIM / 128, B_DIM);
    wsum_kernel<<<g3, 256>>>(x, weights, out);
}